// round 13
// baseline (speedup 1.0000x reference)
#include <cuda_runtime.h>
#include <cuda_fp16.h>
#include <cstdint>
#include <math.h>

// sLSTM cell: plain-fp16 GEMM via mma.sync (HMMA, fp32 accum) + fused epilogue.
// R13: R12 + per-gate staggered stage-full mbarriers. Loads ordered A,B0..B3 with
// an arrive.noinc after each gate tile; consumer warp of gate g waits only on
// barrier g (covers A+B0..Bg). De-synchronizes LDSM bursts (smem crossbar is
// co-binding with the tensor pipe) and shortens the post-wait critical path.

namespace {
constexpr int BATCH = 4096;
constexpr int DH    = 2048;
constexpr int KTOT  = 3072;

constexpr int BM = 64;
constexpr int BN = 64;               // cols per gate
constexpr int BK = 64;               // 128B rows in fp16
constexpr int NCH = KTOT / BK;       // 48

constexpr int A_TILE = BM * BK * 2;              // 8192 B
constexpr int B_TILE = BN * BK * 2;              // 8192 B per gate
constexpr int OFF_A  = 0;
constexpr int OFF_B  = A_TILE;                   // 8192 (+ g*8192)
constexpr int STAGE  = OFF_B + 4 * B_TILE;       // 40960
constexpr int PRE_LD = 68;

constexpr int MB_OFF   = 2 * STAGE;              // 81920: 8 full + 2 empty mbarriers
constexpr int SMEM_REQ = MB_OFF + 96;            // 82016

constexpr float LOG2E = 1.4426950408889634f;

constexpr int A_SEGS = BATCH * 384;              // 8-float segments in A (prepass)
constexpr int B_SEGS = 4 * DH * 384;             // 8-float segments in B (prepass)
} // namespace

__device__ __half g_A[(size_t)BATCH * KTOT];
__device__ __half g_B[(size_t)4 * DH * KTOT];

__device__ __forceinline__ uint32_t smem_u32(const void* p) {
    uint32_t a;
    asm("{ .reg .u64 t; cvta.to.shared.u64 t, %1; cvt.u32.u64 %0, t; }" : "=r"(a) : "l"(p));
    return a;
}
__device__ __forceinline__ void cp_async16(uint32_t dst, const void* src) {
    asm volatile("cp.async.cg.shared.global [%0], [%1], 16;" :: "r"(dst), "l"(src) : "memory");
}

#define MBARRIER_INIT(addr, cnt) \
    asm volatile("mbarrier.init.shared.b64 [%0], %1;" :: "r"((uint32_t)(addr)), "r"((uint32_t)(cnt)) : "memory")

#define MBARRIER_ARRIVE(addr) \
    asm volatile("mbarrier.arrive.shared.b64 _, [%0];" :: "r"((uint32_t)(addr)) : "memory")

#define CPASYNC_MBAR_ARRIVE(addr) \
    asm volatile("cp.async.mbarrier.arrive.noinc.shared.b64 [%0];" :: "r"((uint32_t)(addr)) : "memory")

#define MBARRIER_WAIT_PARITY(addr, par) do {                                              \
    uint32_t _m = (uint32_t)(addr); uint32_t _p = (uint32_t)(par); uint32_t _d;           \
    asm volatile("{ .reg .pred p; mbarrier.try_wait.parity.acquire.cta.shared::cta.b64 p, [%1], %2; selp.b32 %0,1,0,p; }" \
                 : "=r"(_d) : "r"(_m), "r"(_p) : "memory");                               \
    if (!_d) {                                                                            \
        asm volatile("{ .reg .pred P1; WL_%=: mbarrier.try_wait.parity.acquire.cta.shared::cta.b64 P1, [%0], %1, 0x989680; @P1 bra.uni WD_%=; bra.uni WL_%=; WD_%=: }" \
                     :: "r"(_m), "r"(_p) : "memory");                                     \
    }                                                                                     \
} while (0)

__device__ __forceinline__ void ldm_x4(uint32_t* r, uint32_t addr) {
    asm volatile("ldmatrix.sync.aligned.m8n8.x4.shared.b16 {%0,%1,%2,%3}, [%4];"
                 : "=r"(r[0]), "=r"(r[1]), "=r"(r[2]), "=r"(r[3]) : "r"(addr));
}
__device__ __forceinline__ void mma_f16(float* d, const uint32_t* a, const uint32_t* b) {
    asm volatile("mma.sync.aligned.m16n8k16.row.col.f32.f16.f16.f32 "
                 "{%0,%1,%2,%3}, {%4,%5,%6,%7}, {%8,%9}, {%0,%1,%2,%3};"
                 : "+f"(d[0]), "+f"(d[1]), "+f"(d[2]), "+f"(d[3])
                 : "r"(a[0]), "r"(a[1]), "r"(a[2]), "r"(a[3]), "r"(b[0]), "r"(b[1]));
}
__device__ __forceinline__ float ex2f(float x) {
    float y; asm("ex2.approx.f32 %0, %1;" : "=f"(y) : "f"(x)); return y;
}
__device__ __forceinline__ float rcpf(float x) {
    float y; asm("rcp.approx.f32 %0, %1;" : "=f"(y) : "f"(x)); return y;
}
#define SW128(off) ((off) ^ (((off) >> 3) & 0x70))

// ---- fp32x8 -> fp16x8 packed as uint4 ----
__device__ __forceinline__ uint4 pack8(const float4 a, const float4 b) {
    __half2 h0(__float2half_rn(a.x), __float2half_rn(a.y));
    __half2 h1(__float2half_rn(a.z), __float2half_rn(a.w));
    __half2 h2(__float2half_rn(b.x), __float2half_rn(b.y));
    __half2 h3(__float2half_rn(b.z), __float2half_rn(b.w));
    uint4 u;
    u.x = *reinterpret_cast<uint32_t*>(&h0);
    u.y = *reinterpret_cast<uint32_t*>(&h1);
    u.z = *reinterpret_cast<uint32_t*>(&h2);
    u.w = *reinterpret_cast<uint32_t*>(&h3);
    return u;
}

// ---------------- merged prepass: A (x|h_prev) + B (4x W|R), one launch ----------------
__global__ void __launch_bounds__(256)
cvt_all_kernel(const float* __restrict__ x, const float* __restrict__ h_prev,
               const float* __restrict__ W0, const float* __restrict__ W1,
               const float* __restrict__ W2, const float* __restrict__ W3,
               const float* __restrict__ R0, const float* __restrict__ R1,
               const float* __restrict__ R2, const float* __restrict__ R3,
               __half* __restrict__ dA, __half* __restrict__ dB)
{
    const int i = blockIdx.x * blockDim.x + threadIdx.x;
    if (i < A_SEGS) {
        const int row = i / 384;
        const int sg  = i - row * 384;
        float4 va, vb;
        if (sg < 128) {
            const float4* p = reinterpret_cast<const float4*>(x) + row * 256 + sg * 2;
            va = p[0]; vb = p[1];
        } else {
            const float4* p = reinterpret_cast<const float4*>(h_prev) + row * 512 + (sg - 128) * 2;
            va = p[0]; vb = p[1];
        }
        reinterpret_cast<uint4*>(dA + (size_t)row * KTOT)[sg] = pack8(va, vb);
    } else {
        const int j    = i - A_SEGS;
        const int gr   = j / 384;
        const int sg   = j - gr * 384;
        const int gate = gr >> 11;
        const int row  = gr & 2047;
        const float* W = (gate < 2) ? (gate == 0 ? W0 : W1) : (gate == 2 ? W2 : W3);
        const float* R = (gate < 2) ? (gate == 0 ? R0 : R1) : (gate == 2 ? R2 : R3);
        float4 va, vb;
        if (sg < 128) {
            const float4* p = reinterpret_cast<const float4*>(W) + row * 256 + sg * 2;
            va = p[0]; vb = p[1];
        } else {
            const float4* p = reinterpret_cast<const float4*>(R) + row * 512 + (sg - 128) * 2;
            va = p[0]; vb = p[1];
        }
        reinterpret_cast<uint4*>(dB + (size_t)gr * KTOT)[sg] = pack8(va, vb);
    }
}

// ---------------- fused GEMM (HMMA) + sLSTM epilogue ----------------
__global__ void __launch_bounds__(256, 2)
slstm_hmma_kernel(const __half* __restrict__ A, const __half* __restrict__ B,
                  const float* __restrict__ c_prev, const float* __restrict__ n_prev,
                  const float* __restrict__ bz, const float* __restrict__ bi,
                  const float* __restrict__ bf, const float* __restrict__ bo,
                  float* __restrict__ h_out)
{
    extern __shared__ char smem[];
    const uint32_t sbase = smem_u32(smem);

    const int tid  = threadIdx.x;
    const int lane = tid & 31;
    const int wid  = tid >> 5;           // 0..7
    const int gate = wid & 3;
    const int m0   = (wid >> 2) * 32;    // warp rows [m0, m0+32)

    const int row0 = blockIdx.x * BM;    // row-block fast
    const int col0 = blockIdx.y * BN;

    // full barriers: [stage][gate] (count 256; arrive g tracks loads A+B0..Bg)
    // empty barriers: per stage (count 8: lane0 per warp after compute)
    const uint32_t mb_full   = sbase + MB_OFF;            // 8 x 8B
    const uint32_t mb_empty0 = sbase + MB_OFF + 64;
    const uint32_t mb_empty1 = sbase + MB_OFF + 72;
    if (tid == 0) {
#pragma unroll
        for (int b = 0; b < 8; ++b) MBARRIER_INIT(mb_full + b * 8, 256);
        MBARRIER_INIT(mb_empty0, 8);
        MBARRIER_INIT(mb_empty1, 8);
    }
    __syncthreads();

    // ---- stage loader: 10 cp.async(16B) per thread; arrive after each gate ----
    const int lr = tid >> 3;             // 0..31
    const int ls = tid & 7;

    auto load_stage = [&](int s, int k0) {
        const uint32_t st = sbase + s * STAGE;
        const uint32_t fb = mb_full + s * 32;
#pragma unroll
        for (int it = 0; it < 2; ++it) {             // A: 64 rows
            const int r = lr + it * 32;
            const uint32_t off = SW128((uint32_t)(r * 128 + ls * 16));
            const size_t gi = (size_t)(row0 + r) * KTOT + k0 + ls * 8;
            cp_async16(st + OFF_A + off, A + gi);
        }
#pragma unroll
        for (int g = 0; g < 4; ++g) {                // B: 64 rows per gate
#pragma unroll
            for (int it = 0; it < 2; ++it) {
                const int r = lr + it * 32;
                const uint32_t off = SW128((uint32_t)(r * 128 + ls * 16));
                const size_t gi = (size_t)(g * DH + col0 + r) * KTOT + k0 + ls * 8;
                cp_async16(st + OFF_B + g * B_TILE + off, B + gi);
            }
            CPASYNC_MBAR_ARRIVE(fb + g * 8);         // covers A + B0..Bg
        }
    };

    // ---- per-lane ldmatrix address components (validated R3-R12) ----
    const uint32_t xr     = (uint32_t)(lane & 7) << 4;
    const uint32_t a_row  = (uint32_t)(lane & 15);
    const uint32_t a_sel  = (lane & 16) ? 16u : 0u;
    const uint32_t b_rowl = (uint32_t)((lane & 7) + ((lane & 16) ? 8 : 0));
    const uint32_t b_sel  = (lane & 8) ? 16u : 0u;

    float acc[2][8][4];
#pragma unroll
    for (int mt = 0; mt < 2; ++mt)
#pragma unroll
        for (int nt = 0; nt < 8; ++nt)
#pragma unroll
            for (int e = 0; e < 4; ++e) acc[mt][nt][e] = 0.0f;

    // prologue: fill both stages
    load_stage(0, 0);
    load_stage(1, BK);

    const uint32_t my_full0 = mb_full + gate * 8;        // stage 0, my gate
    const uint32_t my_full1 = mb_full + 32 + gate * 8;   // stage 1, my gate
    int pf0 = 0, pf1 = 0, pe0 = 0, pe1 = 0;

#pragma unroll 1
    for (int c = 0; c < NCH; ++c) {
        const int s = c & 1;
        if (s == 0) { MBARRIER_WAIT_PARITY(my_full0, pf0); pf0 ^= 1; }
        else        { MBARRIER_WAIT_PARITY(my_full1, pf1); pf1 ^= 1; }

        const uint32_t st = sbase + s * STAGE;
        const uint32_t aB = st + OFF_A;
        const uint32_t bB = st + OFF_B + gate * B_TILE;

#pragma unroll
        for (int j = 0; j < 4; ++j) {                // k16 steps within BK=64
            const uint32_t akb = ((uint32_t)(j * 32) + a_sel) ^ xr;
            const uint32_t bkb = ((uint32_t)(j * 32) + b_sel) ^ xr;

            uint32_t bh[4][4];
#pragma unroll
            for (int np = 0; np < 4; ++np) {
                const uint32_t rbyte = (np * 16 + b_rowl) * 128;
                ldm_x4(bh[np], bB + rbyte + bkb);
            }
#pragma unroll
            for (int mt = 0; mt < 2; ++mt) {
                uint32_t ah[4];
                const uint32_t rbyte = (m0 + mt * 16 + a_row) * 128;
                ldm_x4(ah, aB + rbyte + akb);
#pragma unroll
                for (int np = 0; np < 4; ++np)
#pragma unroll
                    for (int ss = 0; ss < 2; ++ss)
                        mma_f16(acc[mt][np * 2 + ss], ah, &bh[np][2 * ss]);
            }
        }

        __syncwarp();
        if (lane == 0) MBARRIER_ARRIVE(s == 0 ? mb_empty0 : mb_empty1);

        if (c < NCH - 2) {
            // stage s free once all 8 warps finished chunk c
            if (s == 0) { MBARRIER_WAIT_PARITY(mb_empty0, pe0); pe0 ^= 1; }
            else        { MBARRIER_WAIT_PARITY(mb_empty1, pe1); pe1 ^= 1; }
            load_stage(s, (c + 2) * BK);
        }
    }

    __syncthreads();   // all warps done with tiles before smem reuse

    // ---- exchange gates through smem, then fused sLSTM epilogue ----
    float* pre = reinterpret_cast<float*>(smem);   // [4][64][PRE_LD]
    float* pg = pre + (size_t)gate * BM * PRE_LD;
#pragma unroll
    for (int mt = 0; mt < 2; ++mt) {
        const int r = m0 + mt * 16 + (lane >> 2);
#pragma unroll
        for (int nt = 0; nt < 8; ++nt) {
            const int cc = nt * 8 + (lane & 3) * 2;
            pg[(size_t)r * PRE_LD + cc]           = acc[mt][nt][0];
            pg[(size_t)r * PRE_LD + cc + 1]       = acc[mt][nt][1];
            pg[(size_t)(r + 8) * PRE_LD + cc]     = acc[mt][nt][2];
            pg[(size_t)(r + 8) * PRE_LD + cc + 1] = acc[mt][nt][3];
        }
    }
    __syncthreads();

    {
        const int r     = tid >> 2;            // 0..63
        const int cbase = (tid & 3) * 16;      // 16 cols per thread
        const size_t gbase = (size_t)(row0 + r) * DH + col0 + cbase;
        const int    col   = col0 + cbase;

#pragma unroll
        for (int q = 0; q < 4; ++q) {
            const int cq = cbase + q * 4;
            const float4 bz4 = *reinterpret_cast<const float4*>(bz + col + q * 4);
            const float4 bi4 = *reinterpret_cast<const float4*>(bi + col + q * 4);
            const float4 bf4 = *reinterpret_cast<const float4*>(bf + col + q * 4);
            const float4 bo4 = *reinterpret_cast<const float4*>(bo + col + q * 4);
            const float4 c4  = *reinterpret_cast<const float4*>(c_prev + gbase + q * 4);
            const float4 n4  = *reinterpret_cast<const float4*>(n_prev + gbase + q * 4);
            const float bzr[4] = {bz4.x, bz4.y, bz4.z, bz4.w};
            const float bir[4] = {bi4.x, bi4.y, bi4.z, bi4.w};
            const float bfr[4] = {bf4.x, bf4.y, bf4.z, bf4.w};
            const float bor[4] = {bo4.x, bo4.y, bo4.z, bo4.w};
            const float cpr[4] = {c4.x, c4.y, c4.z, c4.w};
            const float npr[4] = {n4.x, n4.y, n4.z, n4.w};
            float hv[4];
#pragma unroll
            for (int e = 0; e < 4; ++e) {
                const size_t pix = (size_t)r * PRE_LD + cq + e;
                const float az = pre[0 * BM * PRE_LD + pix] + bzr[e];
                const float ai = pre[1 * BM * PRE_LD + pix] + bir[e];
                const float af = pre[2 * BM * PRE_LD + pix] + bfr[e];
                const float ao = pre[3 * BM * PRE_LD + pix] + bor[e];
                const float u  = ex2f(2.0f * LOG2E * az);
                const float z  = 1.0f - 2.0f * rcpf(u + 1.0f);
                const float rv = ex2f(LOG2E * (af - ai));
                const float eo = ex2f(-LOG2E * ao);
                const float num = fmaf(rv, cpr[e], z);
                const float den = fmaf(rv, npr[e], 1.0f) * (1.0f + eo);
                hv[e] = num * rcpf(den);
            }
            *reinterpret_cast<float4*>(h_out + gbase + q * 4) =
                make_float4(hv[0], hv[1], hv[2], hv[3]);
        }
    }
}

// ---------------- launch ----------------
extern "C" void kernel_launch(void* const* d_in, const int* in_sizes, int n_in,
                              void* d_out, int out_size)
{
    const float* x      = (const float*)d_in[0];
    const float* h_prev = (const float*)d_in[1];
    const float* c_prev = (const float*)d_in[2];
    const float* n_prev = (const float*)d_in[3];
    const float* W0 = (const float*)d_in[4];
    const float* W1 = (const float*)d_in[5];
    const float* W2 = (const float*)d_in[6];
    const float* W3 = (const float*)d_in[7];
    const float* bz = (const float*)d_in[8];
    const float* bi = (const float*)d_in[9];
    const float* bf = (const float*)d_in[10];
    const float* bo = (const float*)d_in[11];
    const float* R0 = (const float*)d_in[12];
    const float* R1 = (const float*)d_in[13];
    const float* R2 = (const float*)d_in[14];
    const float* R3 = (const float*)d_in[15];
    float* out = (float*)d_out;

    __half *pA, *pB;
    cudaGetSymbolAddress((void**)&pA, g_A);
    cudaGetSymbolAddress((void**)&pB, g_B);

    cvt_all_kernel<<<(A_SEGS + B_SEGS) / 256, 256>>>(x, h_prev,
                                                     W0, W1, W2, W3, R0, R1, R2, R3,
                                                     pA, pB);

    cudaFuncSetAttribute(slstm_hmma_kernel, cudaFuncAttributeMaxDynamicSharedMemorySize, SMEM_REQ);
    dim3 grid(BATCH / BM, DH / BN);   // (64, 32)
    slstm_hmma_kernel<<<grid, 256, SMEM_REQ>>>(pA, pB,
                                               c_prev, n_prev, bz, bi, bf, bo, out);
}

// round 14
// speedup vs baseline: 1.0961x; 1.0961x over previous
#include <cuda_runtime.h>
#include <cuda_fp16.h>
#include <cstdint>
#include <math.h>

// sLSTM cell: plain-fp16 GEMM via mma.sync (HMMA, fp32 accum) + fused epilogue.
// R14: BM=128, 512 threads, 1 CTA/SM, 4-stage mbarrier ring (warps drift up to
// 3 chunks). Crossbar traffic/SM/chunk drops 272KB -> 240KB (below HMMA floor);
// deep staging hides full-barrier latency without CTA-wide syncs.

namespace {
constexpr int BATCH = 4096;
constexpr int DH    = 2048;
constexpr int KTOT  = 3072;

constexpr int BM = 128;
constexpr int BN = 64;               // cols per gate
constexpr int BK = 64;               // 128B rows in fp16
constexpr int NCH = KTOT / BK;       // 48
constexpr int NST = 4;               // pipeline stages

constexpr int A_TILE = BM * BK * 2;              // 16384 B
constexpr int B_TILE = BN * BK * 2;              // 8192 B per gate
constexpr int OFF_A  = 0;
constexpr int OFF_B  = A_TILE;                   // 16384 (+ g*8192)
constexpr int STAGE  = OFF_B + 4 * B_TILE;       // 49152
constexpr int PRE_LD = 68;

constexpr int MB_OFF   = NST * STAGE;            // 196608: 4 full + 4 empty mbarriers
constexpr int SMEM_REQ = MB_OFF + 128;           // 196736 (pre needs 139264 <= this)

constexpr float LOG2E = 1.4426950408889634f;

constexpr int A_SEGS = BATCH * 384;              // 8-float segments in A (prepass)
constexpr int B_SEGS = 4 * DH * 384;             // 8-float segments in B (prepass)
} // namespace

__device__ __half g_A[(size_t)BATCH * KTOT];
__device__ __half g_B[(size_t)4 * DH * KTOT];

__device__ __forceinline__ uint32_t smem_u32(const void* p) {
    uint32_t a;
    asm("{ .reg .u64 t; cvta.to.shared.u64 t, %1; cvt.u32.u64 %0, t; }" : "=r"(a) : "l"(p));
    return a;
}
__device__ __forceinline__ void cp_async16(uint32_t dst, const void* src) {
    asm volatile("cp.async.cg.shared.global [%0], [%1], 16;" :: "r"(dst), "l"(src) : "memory");
}

#define MBARRIER_INIT(addr, cnt) \
    asm volatile("mbarrier.init.shared.b64 [%0], %1;" :: "r"((uint32_t)(addr)), "r"((uint32_t)(cnt)) : "memory")

#define MBARRIER_ARRIVE(addr) \
    asm volatile("mbarrier.arrive.shared.b64 _, [%0];" :: "r"((uint32_t)(addr)) : "memory")

#define CPASYNC_MBAR_ARRIVE(addr) \
    asm volatile("cp.async.mbarrier.arrive.noinc.shared.b64 [%0];" :: "r"((uint32_t)(addr)) : "memory")

#define MBARRIER_WAIT_PARITY(addr, par) do {                                              \
    uint32_t _m = (uint32_t)(addr); uint32_t _p = (uint32_t)(par); uint32_t _d;           \
    asm volatile("{ .reg .pred p; mbarrier.try_wait.parity.acquire.cta.shared::cta.b64 p, [%1], %2; selp.b32 %0,1,0,p; }" \
                 : "=r"(_d) : "r"(_m), "r"(_p) : "memory");                               \
    if (!_d) {                                                                            \
        asm volatile("{ .reg .pred P1; WL_%=: mbarrier.try_wait.parity.acquire.cta.shared::cta.b64 P1, [%0], %1, 0x989680; @P1 bra.uni WD_%=; bra.uni WL_%=; WD_%=: }" \
                     :: "r"(_m), "r"(_p) : "memory");                                     \
    }                                                                                     \
} while (0)

__device__ __forceinline__ void ldm_x4(uint32_t* r, uint32_t addr) {
    asm volatile("ldmatrix.sync.aligned.m8n8.x4.shared.b16 {%0,%1,%2,%3}, [%4];"
                 : "=r"(r[0]), "=r"(r[1]), "=r"(r[2]), "=r"(r[3]) : "r"(addr));
}
__device__ __forceinline__ void mma_f16(float* d, const uint32_t* a, const uint32_t* b) {
    asm volatile("mma.sync.aligned.m16n8k16.row.col.f32.f16.f16.f32 "
                 "{%0,%1,%2,%3}, {%4,%5,%6,%7}, {%8,%9}, {%0,%1,%2,%3};"
                 : "+f"(d[0]), "+f"(d[1]), "+f"(d[2]), "+f"(d[3])
                 : "r"(a[0]), "r"(a[1]), "r"(a[2]), "r"(a[3]), "r"(b[0]), "r"(b[1]));
}
__device__ __forceinline__ float ex2f(float x) {
    float y; asm("ex2.approx.f32 %0, %1;" : "=f"(y) : "f"(x)); return y;
}
__device__ __forceinline__ float rcpf(float x) {
    float y; asm("rcp.approx.f32 %0, %1;" : "=f"(y) : "f"(x)); return y;
}
#define SW128(off) ((off) ^ (((off) >> 3) & 0x70))

// ---- fp32x8 -> fp16x8 packed as uint4 ----
__device__ __forceinline__ uint4 pack8(const float4 a, const float4 b) {
    __half2 h0(__float2half_rn(a.x), __float2half_rn(a.y));
    __half2 h1(__float2half_rn(a.z), __float2half_rn(a.w));
    __half2 h2(__float2half_rn(b.x), __float2half_rn(b.y));
    __half2 h3(__float2half_rn(b.z), __float2half_rn(b.w));
    uint4 u;
    u.x = *reinterpret_cast<uint32_t*>(&h0);
    u.y = *reinterpret_cast<uint32_t*>(&h1);
    u.z = *reinterpret_cast<uint32_t*>(&h2);
    u.w = *reinterpret_cast<uint32_t*>(&h3);
    return u;
}

// ---------------- merged prepass: A (x|h_prev) + B (4x W|R), one launch ----------------
__global__ void __launch_bounds__(256)
cvt_all_kernel(const float* __restrict__ x, const float* __restrict__ h_prev,
               const float* __restrict__ W0, const float* __restrict__ W1,
               const float* __restrict__ W2, const float* __restrict__ W3,
               const float* __restrict__ R0, const float* __restrict__ R1,
               const float* __restrict__ R2, const float* __restrict__ R3,
               __half* __restrict__ dA, __half* __restrict__ dB)
{
    const int i = blockIdx.x * blockDim.x + threadIdx.x;
    if (i < A_SEGS) {
        const int row = i / 384;
        const int sg  = i - row * 384;
        float4 va, vb;
        if (sg < 128) {
            const float4* p = reinterpret_cast<const float4*>(x) + row * 256 + sg * 2;
            va = p[0]; vb = p[1];
        } else {
            const float4* p = reinterpret_cast<const float4*>(h_prev) + row * 512 + (sg - 128) * 2;
            va = p[0]; vb = p[1];
        }
        reinterpret_cast<uint4*>(dA + (size_t)row * KTOT)[sg] = pack8(va, vb);
    } else {
        const int j    = i - A_SEGS;
        const int gr   = j / 384;
        const int sg   = j - gr * 384;
        const int gate = gr >> 11;
        const int row  = gr & 2047;
        const float* W = (gate < 2) ? (gate == 0 ? W0 : W1) : (gate == 2 ? W2 : W3);
        const float* R = (gate < 2) ? (gate == 0 ? R0 : R1) : (gate == 2 ? R2 : R3);
        float4 va, vb;
        if (sg < 128) {
            const float4* p = reinterpret_cast<const float4*>(W) + row * 256 + sg * 2;
            va = p[0]; vb = p[1];
        } else {
            const float4* p = reinterpret_cast<const float4*>(R) + row * 512 + (sg - 128) * 2;
            va = p[0]; vb = p[1];
        }
        reinterpret_cast<uint4*>(dB + (size_t)gr * KTOT)[sg] = pack8(va, vb);
    }
}

// ---------------- fused GEMM (HMMA) + sLSTM epilogue ----------------
__global__ void __launch_bounds__(512, 1)
slstm_hmma_kernel(const __half* __restrict__ A, const __half* __restrict__ B,
                  const float* __restrict__ c_prev, const float* __restrict__ n_prev,
                  const float* __restrict__ bz, const float* __restrict__ bi,
                  const float* __restrict__ bf, const float* __restrict__ bo,
                  float* __restrict__ h_out)
{
    extern __shared__ char smem[];
    const uint32_t sbase = smem_u32(smem);

    const int tid  = threadIdx.x;
    const int lane = tid & 31;
    const int wid  = tid >> 5;           // 0..15
    const int gate = wid & 3;
    const int m0   = (wid >> 2) * 32;    // warp rows [m0, m0+32) of BM=128

    const int row0 = blockIdx.x * BM;    // row-block fast
    const int col0 = blockIdx.y * BN;

    // full[s] (count 512: per-thread cp.async arrives), empty[s] (count 16: lane0/warp)
    const uint32_t mb_full  = sbase + MB_OFF;        // 4 x 8B
    const uint32_t mb_empty = sbase + MB_OFF + 32;   // 4 x 8B
    if (tid == 0) {
#pragma unroll
        for (int s = 0; s < NST; ++s) {
            MBARRIER_INIT(mb_full + s * 8, 512);
            MBARRIER_INIT(mb_empty + s * 8, 16);
        }
    }
    __syncthreads();

    // ---- stage loader: 6 cp.async(16B) per thread (512 threads, 48 KB stage) ----
    const int lr = tid >> 3;             // 0..63
    const int ls = tid & 7;

    auto load_stage = [&](int s, int k0) {
        const uint32_t st = sbase + s * STAGE;
#pragma unroll
        for (int it = 0; it < 2; ++it) {             // A: 128 rows
            const int r = lr + it * 64;
            const uint32_t off = SW128((uint32_t)(r * 128 + ls * 16));
            const size_t gi = (size_t)(row0 + r) * KTOT + k0 + ls * 8;
            cp_async16(st + OFF_A + off, A + gi);
        }
        {
            const uint32_t off = SW128((uint32_t)(lr * 128 + ls * 16));
#pragma unroll
            for (int g = 0; g < 4; ++g) {            // B: 64 rows per gate, 1 seg/thread
                const size_t gi = (size_t)(g * DH + col0 + lr) * KTOT + k0 + ls * 8;
                cp_async16(st + OFF_B + g * B_TILE + off, B + gi);
            }
        }
        CPASYNC_MBAR_ARRIVE(mb_full + s * 8);
    };

    // ---- per-lane ldmatrix address components (validated R3-R13) ----
    const uint32_t xr     = (uint32_t)(lane & 7) << 4;
    const uint32_t a_row  = (uint32_t)(lane & 15);
    const uint32_t a_sel  = (lane & 16) ? 16u : 0u;
    const uint32_t b_rowl = (uint32_t)((lane & 7) + ((lane & 16) ? 8 : 0));
    const uint32_t b_sel  = (lane & 8) ? 16u : 0u;

    float acc[2][8][4];
#pragma unroll
    for (int mt = 0; mt < 2; ++mt)
#pragma unroll
        for (int nt = 0; nt < 8; ++nt)
#pragma unroll
            for (int e = 0; e < 4; ++e) acc[mt][nt][e] = 0.0f;

    // prologue: fill 3 of 4 stages
    load_stage(0, 0);
    load_stage(1, BK);
    load_stage(2, 2 * BK);

#pragma unroll 1
    for (int c = 0; c < NCH; ++c) {
        const int s = c & 3;
        MBARRIER_WAIT_PARITY(mb_full + s * 8, (c >> 2) & 1);

        const uint32_t st = sbase + s * STAGE;
        const uint32_t aB = st + OFF_A;
        const uint32_t bB = st + OFF_B + gate * B_TILE;

#pragma unroll
        for (int j = 0; j < 4; ++j) {                // k16 steps within BK=64
            const uint32_t akb = ((uint32_t)(j * 32) + a_sel) ^ xr;
            const uint32_t bkb = ((uint32_t)(j * 32) + b_sel) ^ xr;

            uint32_t bh[4][4];
#pragma unroll
            for (int np = 0; np < 4; ++np) {
                const uint32_t rbyte = (np * 16 + b_rowl) * 128;
                ldm_x4(bh[np], bB + rbyte + bkb);
            }
#pragma unroll
            for (int mt = 0; mt < 2; ++mt) {
                uint32_t ah[4];
                const uint32_t rbyte = (m0 + mt * 16 + a_row) * 128;
                ldm_x4(ah, aB + rbyte + akb);
#pragma unroll
                for (int np = 0; np < 4; ++np)
#pragma unroll
                    for (int ss = 0; ss < 2; ++ss)
                        mma_f16(acc[mt][np * 2 + ss], ah, &bh[np][2 * ss]);
            }
        }

        __syncwarp();
        if (lane == 0) MBARRIER_ARRIVE(mb_empty + s * 8);

        const int l = c + 3;                         // keep 3 stages in flight
        if (l < NCH) {
            const int sl = l & 3;
            if (l >= NST) MBARRIER_WAIT_PARITY(mb_empty + sl * 8, ((l - NST) >> 2) & 1);
            load_stage(sl, l * BK);
        }
    }

    __syncthreads();   // all warps done with tiles before smem reuse

    // ---- exchange gates through smem, then fused sLSTM epilogue ----
    float* pre = reinterpret_cast<float*>(smem);   // [4][128][PRE_LD]
    float* pg = pre + (size_t)gate * BM * PRE_LD;
#pragma unroll
    for (int mt = 0; mt < 2; ++mt) {
        const int r = m0 + mt * 16 + (lane >> 2);
#pragma unroll
        for (int nt = 0; nt < 8; ++nt) {
            const int cc = nt * 8 + (lane & 3) * 2;
            pg[(size_t)r * PRE_LD + cc]           = acc[mt][nt][0];
            pg[(size_t)r * PRE_LD + cc + 1]       = acc[mt][nt][1];
            pg[(size_t)(r + 8) * PRE_LD + cc]     = acc[mt][nt][2];
            pg[(size_t)(r + 8) * PRE_LD + cc + 1] = acc[mt][nt][3];
        }
    }
    __syncthreads();

    {
        const int r     = tid >> 2;            // 0..127
        const int cbase = (tid & 3) * 16;      // 16 cols per thread
        const size_t gbase = (size_t)(row0 + r) * DH + col0 + cbase;
        const int    col   = col0 + cbase;

#pragma unroll
        for (int q = 0; q < 4; ++q) {
            const int cq = cbase + q * 4;
            const float4 bz4 = *reinterpret_cast<const float4*>(bz + col + q * 4);
            const float4 bi4 = *reinterpret_cast<const float4*>(bi + col + q * 4);
            const float4 bf4 = *reinterpret_cast<const float4*>(bf + col + q * 4);
            const float4 bo4 = *reinterpret_cast<const float4*>(bo + col + q * 4);
            const float4 c4  = *reinterpret_cast<const float4*>(c_prev + gbase + q * 4);
            const float4 n4  = *reinterpret_cast<const float4*>(n_prev + gbase + q * 4);
            const float bzr[4] = {bz4.x, bz4.y, bz4.z, bz4.w};
            const float bir[4] = {bi4.x, bi4.y, bi4.z, bi4.w};
            const float bfr[4] = {bf4.x, bf4.y, bf4.z, bf4.w};
            const float bor[4] = {bo4.x, bo4.y, bo4.z, bo4.w};
            const float cpr[4] = {c4.x, c4.y, c4.z, c4.w};
            const float npr[4] = {n4.x, n4.y, n4.z, n4.w};
            float hv[4];
#pragma unroll
            for (int e = 0; e < 4; ++e) {
                const size_t pix = (size_t)r * PRE_LD + cq + e;
                const float az = pre[0 * BM * PRE_LD + pix] + bzr[e];
                const float ai = pre[1 * BM * PRE_LD + pix] + bir[e];
                const float af = pre[2 * BM * PRE_LD + pix] + bfr[e];
                const float ao = pre[3 * BM * PRE_LD + pix] + bor[e];
                const float u  = ex2f(2.0f * LOG2E * az);
                const float z  = 1.0f - 2.0f * rcpf(u + 1.0f);
                const float rv = ex2f(LOG2E * (af - ai));
                const float eo = ex2f(-LOG2E * ao);
                const float num = fmaf(rv, cpr[e], z);
                const float den = fmaf(rv, npr[e], 1.0f) * (1.0f + eo);
                hv[e] = num * rcpf(den);
            }
            *reinterpret_cast<float4*>(h_out + gbase + q * 4) =
                make_float4(hv[0], hv[1], hv[2], hv[3]);
        }
    }
}

// ---------------- launch ----------------
extern "C" void kernel_launch(void* const* d_in, const int* in_sizes, int n_in,
                              void* d_out, int out_size)
{
    const float* x      = (const float*)d_in[0];
    const float* h_prev = (const float*)d_in[1];
    const float* c_prev = (const float*)d_in[2];
    const float* n_prev = (const float*)d_in[3];
    const float* W0 = (const float*)d_in[4];
    const float* W1 = (const float*)d_in[5];
    const float* W2 = (const float*)d_in[6];
    const float* W3 = (const float*)d_in[7];
    const float* bz = (const float*)d_in[8];
    const float* bi = (const float*)d_in[9];
    const float* bf = (const float*)d_in[10];
    const float* bo = (const float*)d_in[11];
    const float* R0 = (const float*)d_in[12];
    const float* R1 = (const float*)d_in[13];
    const float* R2 = (const float*)d_in[14];
    const float* R3 = (const float*)d_in[15];
    float* out = (float*)d_out;

    __half *pA, *pB;
    cudaGetSymbolAddress((void**)&pA, g_A);
    cudaGetSymbolAddress((void**)&pB, g_B);

    cvt_all_kernel<<<(A_SEGS + B_SEGS) / 256, 256>>>(x, h_prev,
                                                     W0, W1, W2, W3, R0, R1, R2, R3,
                                                     pA, pB);

    cudaFuncSetAttribute(slstm_hmma_kernel, cudaFuncAttributeMaxDynamicSharedMemorySize, SMEM_REQ);
    dim3 grid(BATCH / BM, DH / BN);   // (32, 32)
    slstm_hmma_kernel<<<grid, 512, SMEM_REQ>>>(pA, pB,
                                               c_prev, n_prev, bz, bi, bf, bo, out);
}

// round 15
// speedup vs baseline: 1.1456x; 1.0452x over previous
#include <cuda_runtime.h>
#include <cuda_fp16.h>
#include <cstdint>
#include <math.h>

// sLSTM cell: plain-fp16 GEMM via mma.sync (HMMA, fp32 accum) + fused epilogue.
// R15: 8 fat warps (64x64 warp tile, 256 threads, ~190 regs), 1 CTA/SM, 4-stage
// mbarrier ring. Halves LDSM crossbar traffic (192KB -> 128KB per chunk per SM),
// taking the smem pipe out of co-binding with the tensor pipe.

namespace {
constexpr int BATCH = 4096;
constexpr int DH    = 2048;
constexpr int KTOT  = 3072;

constexpr int BM = 128;
constexpr int BN = 64;               // cols per gate
constexpr int BK = 64;               // 128B rows in fp16
constexpr int NCH = KTOT / BK;       // 48
constexpr int NST = 4;               // pipeline stages

constexpr int A_TILE = BM * BK * 2;              // 16384 B
constexpr int B_TILE = BN * BK * 2;              // 8192 B per gate
constexpr int OFF_A  = 0;
constexpr int OFF_B  = A_TILE;                   // 16384 (+ g*8192)
constexpr int STAGE  = OFF_B + 4 * B_TILE;       // 49152
constexpr int PRE_LD = 68;

constexpr int MB_OFF   = NST * STAGE;            // 196608: 4 full + 4 empty mbarriers
constexpr int SMEM_REQ = MB_OFF + 128;           // 196736 (pre needs 139264 <= this)

constexpr float LOG2E = 1.4426950408889634f;

constexpr int A_SEGS = BATCH * 384;              // 8-float segments in A (prepass)
constexpr int B_SEGS = 4 * DH * 384;             // 8-float segments in B (prepass)
} // namespace

__device__ __half g_A[(size_t)BATCH * KTOT];
__device__ __half g_B[(size_t)4 * DH * KTOT];

__device__ __forceinline__ uint32_t smem_u32(const void* p) {
    uint32_t a;
    asm("{ .reg .u64 t; cvta.to.shared.u64 t, %1; cvt.u32.u64 %0, t; }" : "=r"(a) : "l"(p));
    return a;
}
__device__ __forceinline__ void cp_async16(uint32_t dst, const void* src) {
    asm volatile("cp.async.cg.shared.global [%0], [%1], 16;" :: "r"(dst), "l"(src) : "memory");
}

#define MBARRIER_INIT(addr, cnt) \
    asm volatile("mbarrier.init.shared.b64 [%0], %1;" :: "r"((uint32_t)(addr)), "r"((uint32_t)(cnt)) : "memory")

#define MBARRIER_ARRIVE(addr) \
    asm volatile("mbarrier.arrive.shared.b64 _, [%0];" :: "r"((uint32_t)(addr)) : "memory")

#define CPASYNC_MBAR_ARRIVE(addr) \
    asm volatile("cp.async.mbarrier.arrive.noinc.shared.b64 [%0];" :: "r"((uint32_t)(addr)) : "memory")

#define MBARRIER_WAIT_PARITY(addr, par) do {                                              \
    uint32_t _m = (uint32_t)(addr); uint32_t _p = (uint32_t)(par); uint32_t _d;           \
    asm volatile("{ .reg .pred p; mbarrier.try_wait.parity.acquire.cta.shared::cta.b64 p, [%1], %2; selp.b32 %0,1,0,p; }" \
                 : "=r"(_d) : "r"(_m), "r"(_p) : "memory");                               \
    if (!_d) {                                                                            \
        asm volatile("{ .reg .pred P1; WL_%=: mbarrier.try_wait.parity.acquire.cta.shared::cta.b64 P1, [%0], %1, 0x989680; @P1 bra.uni WD_%=; bra.uni WL_%=; WD_%=: }" \
                     :: "r"(_m), "r"(_p) : "memory");                                     \
    }                                                                                     \
} while (0)

__device__ __forceinline__ void ldm_x4(uint32_t* r, uint32_t addr) {
    asm volatile("ldmatrix.sync.aligned.m8n8.x4.shared.b16 {%0,%1,%2,%3}, [%4];"
                 : "=r"(r[0]), "=r"(r[1]), "=r"(r[2]), "=r"(r[3]) : "r"(addr));
}
__device__ __forceinline__ void mma_f16(float* d, const uint32_t* a, const uint32_t* b) {
    asm volatile("mma.sync.aligned.m16n8k16.row.col.f32.f16.f16.f32 "
                 "{%0,%1,%2,%3}, {%4,%5,%6,%7}, {%8,%9}, {%0,%1,%2,%3};"
                 : "+f"(d[0]), "+f"(d[1]), "+f"(d[2]), "+f"(d[3])
                 : "r"(a[0]), "r"(a[1]), "r"(a[2]), "r"(a[3]), "r"(b[0]), "r"(b[1]));
}
__device__ __forceinline__ float ex2f(float x) {
    float y; asm("ex2.approx.f32 %0, %1;" : "=f"(y) : "f"(x)); return y;
}
__device__ __forceinline__ float rcpf(float x) {
    float y; asm("rcp.approx.f32 %0, %1;" : "=f"(y) : "f"(x)); return y;
}
#define SW128(off) ((off) ^ (((off) >> 3) & 0x70))

// ---- fp32x8 -> fp16x8 packed as uint4 ----
__device__ __forceinline__ uint4 pack8(const float4 a, const float4 b) {
    __half2 h0(__float2half_rn(a.x), __float2half_rn(a.y));
    __half2 h1(__float2half_rn(a.z), __float2half_rn(a.w));
    __half2 h2(__float2half_rn(b.x), __float2half_rn(b.y));
    __half2 h3(__float2half_rn(b.z), __float2half_rn(b.w));
    uint4 u;
    u.x = *reinterpret_cast<uint32_t*>(&h0);
    u.y = *reinterpret_cast<uint32_t*>(&h1);
    u.z = *reinterpret_cast<uint32_t*>(&h2);
    u.w = *reinterpret_cast<uint32_t*>(&h3);
    return u;
}

// ---------------- merged prepass: A (x|h_prev) + B (4x W|R), one launch ----------------
__global__ void __launch_bounds__(256)
cvt_all_kernel(const float* __restrict__ x, const float* __restrict__ h_prev,
               const float* __restrict__ W0, const float* __restrict__ W1,
               const float* __restrict__ W2, const float* __restrict__ W3,
               const float* __restrict__ R0, const float* __restrict__ R1,
               const float* __restrict__ R2, const float* __restrict__ R3,
               __half* __restrict__ dA, __half* __restrict__ dB)
{
    const int i = blockIdx.x * blockDim.x + threadIdx.x;
    if (i < A_SEGS) {
        const int row = i / 384;
        const int sg  = i - row * 384;
        float4 va, vb;
        if (sg < 128) {
            const float4* p = reinterpret_cast<const float4*>(x) + row * 256 + sg * 2;
            va = p[0]; vb = p[1];
        } else {
            const float4* p = reinterpret_cast<const float4*>(h_prev) + row * 512 + (sg - 128) * 2;
            va = p[0]; vb = p[1];
        }
        reinterpret_cast<uint4*>(dA + (size_t)row * KTOT)[sg] = pack8(va, vb);
    } else {
        const int j    = i - A_SEGS;
        const int gr   = j / 384;
        const int sg   = j - gr * 384;
        const int gate = gr >> 11;
        const int row  = gr & 2047;
        const float* W = (gate < 2) ? (gate == 0 ? W0 : W1) : (gate == 2 ? W2 : W3);
        const float* R = (gate < 2) ? (gate == 0 ? R0 : R1) : (gate == 2 ? R2 : R3);
        float4 va, vb;
        if (sg < 128) {
            const float4* p = reinterpret_cast<const float4*>(W) + row * 256 + sg * 2;
            va = p[0]; vb = p[1];
        } else {
            const float4* p = reinterpret_cast<const float4*>(R) + row * 512 + (sg - 128) * 2;
            va = p[0]; vb = p[1];
        }
        reinterpret_cast<uint4*>(dB + (size_t)gr * KTOT)[sg] = pack8(va, vb);
    }
}

// ---------------- fused GEMM (HMMA) + sLSTM epilogue ----------------
__global__ void __launch_bounds__(256, 1)
slstm_hmma_kernel(const __half* __restrict__ A, const __half* __restrict__ B,
                  const float* __restrict__ c_prev, const float* __restrict__ n_prev,
                  const float* __restrict__ bz, const float* __restrict__ bi,
                  const float* __restrict__ bf, const float* __restrict__ bo,
                  float* __restrict__ h_out)
{
    extern __shared__ char smem[];
    const uint32_t sbase = smem_u32(smem);

    const int tid  = threadIdx.x;
    const int lane = tid & 31;
    const int wid  = tid >> 5;           // 0..7
    const int gate = wid & 3;
    const int m0   = (wid >> 2) * 64;    // warp rows [m0, m0+64) of BM=128

    const int row0 = blockIdx.x * BM;    // row-block fast
    const int col0 = blockIdx.y * BN;

    // full[s] (count 256: per-thread cp.async arrives), empty[s] (count 8: lane0/warp)
    const uint32_t mb_full  = sbase + MB_OFF;        // 4 x 8B
    const uint32_t mb_empty = sbase + MB_OFF + 32;   // 4 x 8B
    if (tid == 0) {
#pragma unroll
        for (int s = 0; s < NST; ++s) {
            MBARRIER_INIT(mb_full + s * 8, 256);
            MBARRIER_INIT(mb_empty + s * 8, 8);
        }
    }
    __syncthreads();

    // ---- stage loader: 12 cp.async(16B) per thread (256 threads, 48 KB stage) ----
    const int lr = tid >> 3;             // 0..31
    const int ls = tid & 7;

    auto load_stage = [&](int s, int k0) {
        const uint32_t st = sbase + s * STAGE;
#pragma unroll
        for (int it = 0; it < 4; ++it) {             // A: 128 rows
            const int r = lr + it * 32;
            const uint32_t off = SW128((uint32_t)(r * 128 + ls * 16));
            const size_t gi = (size_t)(row0 + r) * KTOT + k0 + ls * 8;
            cp_async16(st + OFF_A + off, A + gi);
        }
#pragma unroll
        for (int g = 0; g < 4; ++g) {                // B: 64 rows per gate
#pragma unroll
            for (int it = 0; it < 2; ++it) {
                const int r = lr + it * 32;
                const uint32_t off = SW128((uint32_t)(r * 128 + ls * 16));
                const size_t gi = (size_t)(g * DH + col0 + r) * KTOT + k0 + ls * 8;
                cp_async16(st + OFF_B + g * B_TILE + off, B + gi);
            }
        }
        CPASYNC_MBAR_ARRIVE(mb_full + s * 8);
    };

    // ---- per-lane ldmatrix address components (validated R3-R14) ----
    const uint32_t xr     = (uint32_t)(lane & 7) << 4;
    const uint32_t a_row  = (uint32_t)(lane & 15);
    const uint32_t a_sel  = (lane & 16) ? 16u : 0u;
    const uint32_t b_rowl = (uint32_t)((lane & 7) + ((lane & 16) ? 8 : 0));
    const uint32_t b_sel  = (lane & 8) ? 16u : 0u;

    float acc[4][8][4];                  // 64 rows x 64 cols per warp
#pragma unroll
    for (int mt = 0; mt < 4; ++mt)
#pragma unroll
        for (int nt = 0; nt < 8; ++nt)
#pragma unroll
            for (int e = 0; e < 4; ++e) acc[mt][nt][e] = 0.0f;

    // prologue: fill 3 of 4 stages
    load_stage(0, 0);
    load_stage(1, BK);
    load_stage(2, 2 * BK);

#pragma unroll 1
    for (int c = 0; c < NCH; ++c) {
        const int s = c & 3;
        MBARRIER_WAIT_PARITY(mb_full + s * 8, (c >> 2) & 1);

        const uint32_t st = sbase + s * STAGE;
        const uint32_t aB = st + OFF_A;
        const uint32_t bB = st + OFF_B + gate * B_TILE;

#pragma unroll
        for (int j = 0; j < 4; ++j) {                // k16 steps within BK=64
            const uint32_t akb = ((uint32_t)(j * 32) + a_sel) ^ xr;
            const uint32_t bkb = ((uint32_t)(j * 32) + b_sel) ^ xr;

            uint32_t bh[4][4];
#pragma unroll
            for (int np = 0; np < 4; ++np) {
                const uint32_t rbyte = (np * 16 + b_rowl) * 128;
                ldm_x4(bh[np], bB + rbyte + bkb);
            }
#pragma unroll
            for (int mt = 0; mt < 4; ++mt) {
                uint32_t ah[4];
                const uint32_t rbyte = (m0 + mt * 16 + a_row) * 128;
                ldm_x4(ah, aB + rbyte + akb);
#pragma unroll
                for (int np = 0; np < 4; ++np)
#pragma unroll
                    for (int ss = 0; ss < 2; ++ss)
                        mma_f16(acc[mt][np * 2 + ss], ah, &bh[np][2 * ss]);
            }
        }

        __syncwarp();
        if (lane == 0) MBARRIER_ARRIVE(mb_empty + s * 8);

        const int l = c + 3;                         // keep 3 stages in flight
        if (l < NCH) {
            const int sl = l & 3;
            if (l >= NST) MBARRIER_WAIT_PARITY(mb_empty + sl * 8, ((l - NST) >> 2) & 1);
            load_stage(sl, l * BK);
        }
    }

    __syncthreads();   // all warps done with tiles before smem reuse

    // ---- exchange gates through smem, then fused sLSTM epilogue ----
    float* pre = reinterpret_cast<float*>(smem);   // [4][128][PRE_LD]
    float* pg = pre + (size_t)gate * BM * PRE_LD;
#pragma unroll
    for (int mt = 0; mt < 4; ++mt) {
        const int r = m0 + mt * 16 + (lane >> 2);
#pragma unroll
        for (int nt = 0; nt < 8; ++nt) {
            const int cc = nt * 8 + (lane & 3) * 2;
            pg[(size_t)r * PRE_LD + cc]           = acc[mt][nt][0];
            pg[(size_t)r * PRE_LD + cc + 1]       = acc[mt][nt][1];
            pg[(size_t)(r + 8) * PRE_LD + cc]     = acc[mt][nt][2];
            pg[(size_t)(r + 8) * PRE_LD + cc + 1] = acc[mt][nt][3];
        }
    }
    __syncthreads();

    {
        const int r     = tid >> 1;            // 0..127
        const int cbase = (tid & 1) * 32;      // 32 cols per thread
        const size_t gbase = (size_t)(row0 + r) * DH + col0 + cbase;
        const int    col   = col0 + cbase;

#pragma unroll
        for (int q = 0; q < 8; ++q) {
            const int cq = cbase + q * 4;
            const float4 bz4 = *reinterpret_cast<const float4*>(bz + col + q * 4);
            const float4 bi4 = *reinterpret_cast<const float4*>(bi + col + q * 4);
            const float4 bf4 = *reinterpret_cast<const float4*>(bf + col + q * 4);
            const float4 bo4 = *reinterpret_cast<const float4*>(bo + col + q * 4);
            const float4 c4  = *reinterpret_cast<const float4*>(c_prev + gbase + q * 4);
            const float4 n4  = *reinterpret_cast<const float4*>(n_prev + gbase + q * 4);
            const float bzr[4] = {bz4.x, bz4.y, bz4.z, bz4.w};
            const float bir[4] = {bi4.x, bi4.y, bi4.z, bi4.w};
            const float bfr[4] = {bf4.x, bf4.y, bf4.z, bf4.w};
            const float bor[4] = {bo4.x, bo4.y, bo4.z, bo4.w};
            const float cpr[4] = {c4.x, c4.y, c4.z, c4.w};
            const float npr[4] = {n4.x, n4.y, n4.z, n4.w};
            float hv[4];
#pragma unroll
            for (int e = 0; e < 4; ++e) {
                const size_t pix = (size_t)r * PRE_LD + cq + e;
                const float az = pre[0 * BM * PRE_LD + pix] + bzr[e];
                const float ai = pre[1 * BM * PRE_LD + pix] + bir[e];
                const float af = pre[2 * BM * PRE_LD + pix] + bfr[e];
                const float ao = pre[3 * BM * PRE_LD + pix] + bor[e];
                const float u  = ex2f(2.0f * LOG2E * az);
                const float z  = 1.0f - 2.0f * rcpf(u + 1.0f);
                const float rv = ex2f(LOG2E * (af - ai));
                const float eo = ex2f(-LOG2E * ao);
                const float num = fmaf(rv, cpr[e], z);
                const float den = fmaf(rv, npr[e], 1.0f) * (1.0f + eo);
                hv[e] = num * rcpf(den);
            }
            *reinterpret_cast<float4*>(h_out + gbase + q * 4) =
                make_float4(hv[0], hv[1], hv[2], hv[3]);
        }
    }
}

// ---------------- launch ----------------
extern "C" void kernel_launch(void* const* d_in, const int* in_sizes, int n_in,
                              void* d_out, int out_size)
{
    const float* x      = (const float*)d_in[0];
    const float* h_prev = (const float*)d_in[1];
    const float* c_prev = (const float*)d_in[2];
    const float* n_prev = (const float*)d_in[3];
    const float* W0 = (const float*)d_in[4];
    const float* W1 = (const float*)d_in[5];
    const float* W2 = (const float*)d_in[6];
    const float* W3 = (const float*)d_in[7];
    const float* bz = (const float*)d_in[8];
    const float* bi = (const float*)d_in[9];
    const float* bf = (const float*)d_in[10];
    const float* bo = (const float*)d_in[11];
    const float* R0 = (const float*)d_in[12];
    const float* R1 = (const float*)d_in[13];
    const float* R2 = (const float*)d_in[14];
    const float* R3 = (const float*)d_in[15];
    float* out = (float*)d_out;

    __half *pA, *pB;
    cudaGetSymbolAddress((void**)&pA, g_A);
    cudaGetSymbolAddress((void**)&pB, g_B);

    cvt_all_kernel<<<(A_SEGS + B_SEGS) / 256, 256>>>(x, h_prev,
                                                     W0, W1, W2, W3, R0, R1, R2, R3,
                                                     pA, pB);

    cudaFuncSetAttribute(slstm_hmma_kernel, cudaFuncAttributeMaxDynamicSharedMemorySize, SMEM_REQ);
    dim3 grid(BATCH / BM, DH / BN);   // (32, 32)
    slstm_hmma_kernel<<<grid, 256, SMEM_REQ>>>(pA, pB,
                                               c_prev, n_prev, bz, bi, bf, bo, out);
}